// round 14
// baseline (speedup 1.0000x reference)
#include <cuda_runtime.h>
#include <cuda_bf16.h>
#include <math.h>
#include <stdint.h>
#include <cstdint>

// Problem shape
#define BB 4
#define TT 2048
#define DD 1024
#define HH 16
#define PP 64
#define FFD 4096
#define ROWS (BB*TT)          // 8192

// ---------------- scratch (device globals; no allocation allowed) -------------
__device__ float g_nX  [ROWS*DD];   // nX during QKV; reused as Vt afterwards
__device__ float g_QKV [3*ROWS*DD];
__device__ float g_NV  [ROWS*DD];
__device__ float g_SS  [ROWS*DD];
__device__ float g_PRE [ROWS*DD];
__device__ float g_PREr[ROWS*DD];
__device__ float g_HID [ROWS*FFD];
__device__ float g_WTS [12*1024*1024];   // transposed+rounded weights: WQ|WK|WV|WO|fW1|fW2

__device__ __forceinline__ float gelu_f(float x) {
    return 0.5f * x * (1.0f + erff(x * 0.70710678118654752440f));
}

__device__ __forceinline__ uint32_t f2tf32(float x) {
    uint32_t u;
    asm("cvt.rna.tf32.f32 %0, %1;" : "=r"(u) : "f"(x));
    return u;
}
__device__ __forceinline__ float roundtf(float x) { return __uint_as_float(f2tf32(x)); }

__device__ __forceinline__ void mma8(float* c, const uint32_t* a, uint32_t b0, uint32_t b1) {
    asm volatile(
        "mma.sync.aligned.m16n8k8.row.col.f32.tf32.tf32.f32 "
        "{%0,%1,%2,%3}, {%4,%5,%6,%7}, {%8,%9}, {%0,%1,%2,%3};\n"
        : "+f"(c[0]), "+f"(c[1]), "+f"(c[2]), "+f"(c[3])
        : "r"(a[0]), "r"(a[1]), "r"(a[2]), "r"(a[3]), "r"(b0), "r"(b1));
}

__device__ __forceinline__ void ldsm4(uint32_t& r0, uint32_t& r1, uint32_t& r2, uint32_t& r3,
                                      uint32_t addr) {
    asm volatile("ldmatrix.sync.aligned.m8n8.x4.shared.b16 {%0,%1,%2,%3}, [%4];"
                 : "=r"(r0), "=r"(r1), "=r"(r2), "=r"(r3) : "r"(addr));
}

__device__ __forceinline__ void cp16(float* dst, const float* src) {
    uint32_t d = (uint32_t)__cvta_generic_to_shared(dst);
    asm volatile("cp.async.cg.shared.global [%0], [%1], 16;\n" :: "r"(d), "l"(src));
}
__device__ __forceinline__ void cp_commit() { asm volatile("cp.async.commit_group;\n"); }
template<int N>
__device__ __forceinline__ void cp_waitN() { asm volatile("cp.async.wait_group %0;\n" :: "n"(N)); }

// ---------------- weight transpose + tf32 round -------------------------------
// mode 0: in is [K][N] row-major.  mode 1: in is [H][K][64], logical col n=h*64+p.
// out: [N][K] row-major, tf32-rounded. grid (K/32, N/32), 256 threads.
__global__ void transpose_round(const float* __restrict__ in, float* __restrict__ out,
                                int K, int N, int mode)
{
    __shared__ float tile[32][33];
    const int k0 = blockIdx.x * 32;
    const int n0 = blockIdx.y * 32;
    const int tx = threadIdx.x & 31;
    const int ty = threadIdx.x >> 5;     // 0..7
    #pragma unroll
    for (int i = 0; i < 4; i++) {
        int k = k0 + ty + i * 8;
        int n = n0 + tx;
        float v;
        if (mode == 0) v = in[(size_t)k * N + n];
        else           v = in[(size_t)(n >> 6) * ((size_t)K * 64) + (size_t)k * 64 + (n & 63)];
        tile[ty + i * 8][tx] = roundtf(v);
    }
    __syncthreads();
    #pragma unroll
    for (int i = 0; i < 4; i++) {
        int n = n0 + ty + i * 8;
        int k = k0 + tx;
        out[(size_t)n * K + k] = tile[tx][ty + i * 8];
    }
}

// ---------------- V transpose: V[b,k,h,p] -> Vt[(b,h)][p][k] -------------------
// grid (TT/32, PP/32, BB*HH), 256 threads. Values already tf32-rounded.
__global__ void v_transpose(const float* __restrict__ V, float* __restrict__ Vt)
{
    __shared__ float tile[32][33];
    const int b = blockIdx.z >> 4, h = blockIdx.z & 15;
    const float* src = V + (size_t)b * TT * DD + h * PP;     // [k][p], row stride DD
    float* dst = Vt + (size_t)blockIdx.z * PP * TT;          // [p][k], row stride TT
    const int k0 = blockIdx.x * 32;
    const int p0 = blockIdx.y * 32;
    const int tx = threadIdx.x & 31;
    const int ty = threadIdx.x >> 5;
    #pragma unroll
    for (int i = 0; i < 4; i++)
        tile[ty + i * 8][tx] = src[(size_t)(k0 + ty + i * 8) * DD + p0 + tx];
    __syncthreads();
    #pragma unroll
    for (int i = 0; i < 4; i++)
        dst[(size_t)(p0 + ty + i * 8) * TT + k0 + tx] = tile[tx][ty + i * 8];
}

// ---------------- LayerNorm (warp-shuffle reduction) ---------------------------
__global__ void ln_kernel(const float* __restrict__ X, const float* __restrict__ gg,
                          const float* __restrict__ bb, const float* __restrict__ res,
                          float* __restrict__ Yfull, float* __restrict__ Yr)
{
    __shared__ float rs[8], rq[8];
    const int row = blockIdx.x;
    const int t = threadIdx.x;
    const int lane = t & 31, w = t >> 5;
    float4 v = ((const float4*)(X + (size_t)row * DD))[t];
    float s = v.x + v.y + v.z + v.w;
    float q = v.x*v.x + v.y*v.y + v.z*v.z + v.w*v.w;
    #pragma unroll
    for (int o = 16; o > 0; o >>= 1) {
        s += __shfl_xor_sync(0xffffffffu, s, o);
        q += __shfl_xor_sync(0xffffffffu, q, o);
    }
    if (lane == 0) { rs[w] = s; rq[w] = q; }
    __syncthreads();
    s = rs[0]+rs[1]+rs[2]+rs[3]+rs[4]+rs[5]+rs[6]+rs[7];
    q = rq[0]+rq[1]+rq[2]+rq[3]+rq[4]+rq[5]+rq[6]+rq[7];
    const float mu  = s * (1.0f/1024.0f);
    const float var = q * (1.0f/1024.0f) - mu*mu;
    const float inv = rsqrtf(var + 1e-5f);
    float4 g4 = ((const float4*)gg)[t];
    float4 b4 = ((const float4*)bb)[t];
    float4 o;
    o.x = (v.x-mu)*inv*g4.x + b4.x;
    o.y = (v.y-mu)*inv*g4.y + b4.y;
    o.z = (v.z-mu)*inv*g4.z + b4.z;
    o.w = (v.w-mu)*inv*g4.w + b4.w;
    if (res) {
        float4 r = ((const float4*)(res + (size_t)row * DD))[t];
        o.x += r.x; o.y += r.y; o.z += r.z; o.w += r.w;
    }
    if (Yfull) ((float4*)(Yfull + (size_t)row * DD))[t] = o;
    if (Yr) {
        float4 rr = make_float4(roundtf(o.x), roundtf(o.y), roundtf(o.z), roundtf(o.w));
        ((float4*)(Yr + (size_t)row * DD))[t] = rr;
    }
}

// ---------------- in-place row softmax (row length 2048, vectorized) ----------
__global__ void softmax_kernel(float* __restrict__ S)
{
    __shared__ float red[8];
    const size_t row = blockIdx.x;
    float4* p = (float4*)(S + row * (size_t)TT);
    const int t = threadIdx.x;            // 256 threads, 2 float4 each
    const int lane = t & 31, w = t >> 5;

    float4 v0 = p[t];
    float4 v1 = p[t + 256];
    float mx = fmaxf(fmaxf(fmaxf(v0.x, v0.y), fmaxf(v0.z, v0.w)),
                     fmaxf(fmaxf(v1.x, v1.y), fmaxf(v1.z, v1.w)));
    #pragma unroll
    for (int o = 16; o > 0; o >>= 1)
        mx = fmaxf(mx, __shfl_xor_sync(0xffffffffu, mx, o));
    if (lane == 0) red[w] = mx;
    __syncthreads();
    mx = fmaxf(fmaxf(fmaxf(red[0], red[1]), fmaxf(red[2], red[3])),
               fmaxf(fmaxf(red[4], red[5]), fmaxf(red[6], red[7])));
    __syncthreads();

    float4 e0, e1;
    e0.x = __expf(v0.x - mx); e0.y = __expf(v0.y - mx);
    e0.z = __expf(v0.z - mx); e0.w = __expf(v0.w - mx);
    e1.x = __expf(v1.x - mx); e1.y = __expf(v1.y - mx);
    e1.z = __expf(v1.z - mx); e1.w = __expf(v1.w - mx);
    float sum = (e0.x + e0.y) + (e0.z + e0.w) + (e1.x + e1.y) + (e1.z + e1.w);
    #pragma unroll
    for (int o = 16; o > 0; o >>= 1)
        sum += __shfl_xor_sync(0xffffffffu, sum, o);
    if (lane == 0) red[w] = sum;
    __syncthreads();
    sum = (red[0]+red[1]) + (red[2]+red[3]) + (red[4]+red[5]) + (red[6]+red[7]);
    const float inv = 1.0f / sum;

    e0.x *= inv; e0.y *= inv; e0.z *= inv; e0.w *= inv;
    e1.x *= inv; e1.y *= inv; e1.z *= inv; e1.w *= inv;
    p[t]       = e0;
    p[t + 256] = e1;
}

// =====================================================================
// Unified tf32 tensor-core GEMM, STAGES-deep cp.async pipeline, ldmatrix frags.
//   C[r][c] = act( scale * sum_k A[r][k]*B(k,c) + bias[c] ) + residual[r][c]
// BMODE: 0 -> B row-major [K,N]
//        2 -> B given as [N, K] row-major (smem tile n-major; B via ldmatrix)
// CVTA: cvt A fragments to tf32 after load (false -> HW RZ truncation or
//       A already rounded).
// =====================================================================
template<int BN, int BMODE, bool CVTA, int STAGES>
__global__ void __launch_bounds__(256, 2) mma_gemm(
    const float* __restrict__ A, int lda, size_t aOffB, size_t aOffH,
    const float* __restrict__ B, int ldb, size_t bOffB, size_t bOffH,
    float*       __restrict__ C, int ldc, size_t cOffB, size_t cOffH,
    int K, const float* __restrict__ bias, const float* __restrict__ residual,
    int act, float scale, int outRound)
{
    constexpr int BM = 128, BK = 32;
    constexpr int NT = BN / 32;
    constexpr int WN = BN / 4;
    constexpr int AROW = BK + 4;                    // 36
    constexpr int A_STAGE = BM * AROW;
    constexpr int BROW = (BMODE == 2) ? (BK + 4) : (BN + 8);
    constexpr int B_STAGE = (BMODE == 2) ? (BN * BROW) : (BK * BROW);

    extern __shared__ float sm[];
    float* AsBase = sm;
    float* BsBase = sm + STAGES * A_STAGE;
    const uint32_t smU = (uint32_t)__cvta_generic_to_shared(sm);
    const uint32_t bsU = smU + STAGES * A_STAGE * 4;

    const int tid  = threadIdx.x;
    const int lane = tid & 31;
    const int warp = tid >> 5;
    const int g  = lane >> 2;
    const int tq = lane & 3;
    const int wmBase = (warp & 1) * 64;
    const int wnBase = (warp >> 1) * WN;

    const int row0 = blockIdx.y * BM;
    const int col0 = blockIdx.x * BN;

    const int zb = blockIdx.z >> 4, zh = blockIdx.z & 15;
    A += (size_t)zb * aOffB + (size_t)zh * aOffH;
    B += (size_t)zb * bOffB + (size_t)zh * bOffH;
    C += (size_t)zb * cOffB + (size_t)zh * cOffH;

    const int nT = K >> 5;

    uint32_t aLane[4];
    #pragma unroll
    for (int mi = 0; mi < 4; mi++) {
        int r = wmBase + mi * 16 + (lane & 15);
        int c = (lane >> 4) << 2;
        aLane[mi] = (uint32_t)((r * AROW + c) * 4);
    }
    uint32_t bLane[NT > 1 ? NT / 2 : 1];
    if (BMODE == 2) {
        #pragma unroll
        for (int np = 0; np < NT / 2; np++) {
            int sel = lane >> 3;
            int nrow = wnBase + np * 16 + ((sel >> 1) << 3) + (lane & 7);
            int c = (sel & 1) << 2;
            bLane[np] = (uint32_t)((nrow * BROW + c) * 4);
        }
    }

    auto issueA = [&](int t, float* dst) {
        const float* Ak = A + (size_t)row0 * lda + t * BK;
        #pragma unroll
        for (int p = 0; p < 4; p++) {
            int chunk = tid + 256 * p;
            int r = chunk >> 3, c = (chunk & 7) * 4;
            cp16(dst + r * AROW + c, Ak + (size_t)r * lda + c);
        }
    };
    auto issueB = [&](int t, float* dst) {
        if (BMODE == 2) {
            constexpr int PB = (BN * 8) / 256;       // 4 for BN=128, 2 for BN=64
            const float* Bk = B + (size_t)col0 * ldb + t * BK;
            #pragma unroll
            for (int p = 0; p < PB; p++) {
                int chunk = tid + 256 * p;
                int r = chunk >> 3, c = (chunk & 7) * 4;
                cp16(dst + r * BROW + c, Bk + (size_t)r * ldb + c);
            }
        } else {
            constexpr int P   = (BN == 128) ? 4 : 2;
            constexpr int CSH = (BN == 128) ? 5 : 4;
            constexpr int CMK = (BN == 128) ? 31 : 15;
            const float* Bk = B + (size_t)(t * BK) * ldb + col0;
            #pragma unroll
            for (int p = 0; p < P; p++) {
                int chunk = tid + 256 * p;
                int k = chunk >> CSH, c = (chunk & CMK) * 4;
                cp16(dst + k * BROW + c, Bk + (size_t)k * ldb + c);
            }
        }
    };

    float acc[4][NT][4];
    #pragma unroll
    for (int i = 0; i < 4; i++)
        #pragma unroll
        for (int j = 0; j < NT; j++)
            #pragma unroll
            for (int l = 0; l < 4; l++) acc[i][j][l] = 0.0f;

    #pragma unroll
    for (int t = 0; t < STAGES - 1; t++) {
        if (t < nT) {
            issueA(t, AsBase + t * A_STAGE);
            issueB(t, BsBase + t * B_STAGE);
            cp_commit();
        }
    }

    int s = 0;
    for (int t = 0; t < nT; t++) {
        int rem = nT - 1 - t;
        if (rem >= STAGES - 2)      cp_waitN<STAGES - 2>();
        else if (STAGES >= 4 && rem == 2) cp_waitN<2>();
        else if (rem == 1)          cp_waitN<1>();
        else                        cp_waitN<0>();
        __syncthreads();

        const uint32_t aBaseS = smU + (uint32_t)(s * A_STAGE * 4);
        const uint32_t bBaseS = bsU + (uint32_t)(s * B_STAGE * 4);
        const float* Bsm = BsBase + s * B_STAGE;

        #pragma unroll
        for (int ks = 0; ks < 4; ks++) {
            const int kb = ks * 8;
            uint32_t bf[NT][2];
            if (BMODE == 2) {
                #pragma unroll
                for (int np = 0; np < NT / 2; np++)
                    ldsm4(bf[2*np][0], bf[2*np][1], bf[2*np+1][0], bf[2*np+1][1],
                          bBaseS + bLane[np] + kb * 4);
            } else {
                #pragma unroll
                for (int ni = 0; ni < NT; ni++) {
                    int n = wnBase + ni * 8 + g;
                    bf[ni][0] = __float_as_uint(Bsm[(size_t)(kb + tq)     * BROW + n]);
                    bf[ni][1] = __float_as_uint(Bsm[(size_t)(kb + tq + 4) * BROW + n]);
                }
            }
            #pragma unroll
            for (int mi = 0; mi < 4; mi++) {
                uint32_t af[4];
                ldsm4(af[0], af[1], af[2], af[3], aBaseS + aLane[mi] + kb * 4);
                if (CVTA) {
                    af[0] = f2tf32(__uint_as_float(af[0]));
                    af[1] = f2tf32(__uint_as_float(af[1]));
                    af[2] = f2tf32(__uint_as_float(af[2]));
                    af[3] = f2tf32(__uint_as_float(af[3]));
                }
                #pragma unroll
                for (int ni = 0; ni < NT; ni++)
                    mma8(acc[mi][ni], af, bf[ni][0], bf[ni][1]);
            }
        }

        int tn = t + STAGES - 1;
        if (tn < nT) {
            int sn = tn - (tn / STAGES) * STAGES;
            issueA(tn, AsBase + sn * A_STAGE);
            issueB(tn, BsBase + sn * B_STAGE);
            cp_commit();
        }
        s++; if (s == STAGES) s = 0;
    }

    #pragma unroll
    for (int mi = 0; mi < 4; mi++) {
        int r0 = row0 + wmBase + mi * 16 + g;
        #pragma unroll
        for (int ni = 0; ni < NT; ni++) {
            int col = col0 + wnBase + ni * 8 + 2 * tq;
            float b0 = 0.0f, b1 = 0.0f;
            if (bias) { b0 = bias[col]; b1 = bias[col + 1]; }
            #pragma unroll
            for (int half = 0; half < 2; half++) {
                int r = r0 + half * 8;
                float x0 = acc[mi][ni][half*2 + 0] * scale + b0;
                float x1 = acc[mi][ni][half*2 + 1] * scale + b1;
                if (act) { x0 = gelu_f(x0); x1 = gelu_f(x1); }
                if (residual) {
                    float2 rr = *(const float2*)(residual + (size_t)r * ldc + col);
                    x0 += rr.x; x1 += rr.y;
                }
                if (outRound) { x0 = roundtf(x0); x1 = roundtf(x1); }
                *(float2*)(C + (size_t)r * ldc + col) = make_float2(x0, x1);
            }
        }
    }
}

// smem sizes (bytes)
static constexpr size_t smemBytes(int BN, int BMODE, int stages) {
    size_t aStage = 128 * 36;
    size_t bStage = (BMODE == 2) ? (size_t)BN * 36 : (size_t)32 * (BN + 8);
    return (size_t)stages * (aStage + bStage) * 4;
}

// -----------------------------------------------------------------------------
extern "C" void kernel_launch(void* const* d_in, const int* in_sizes, int n_in,
                              void* d_out, int out_size)
{
    const float* X      = (const float*)d_in[0];
    const float* WQ     = (const float*)d_in[1];
    const float* WK     = (const float*)d_in[2];
    const float* WV     = (const float*)d_in[3];
    const float* WO     = (const float*)d_in[4];
    const float* attn_g = (const float*)d_in[5];
    const float* attn_b = (const float*)d_in[6];
    const float* ff_g   = (const float*)d_in[7];
    const float* ff_b   = (const float*)d_in[8];
    const float* fW1    = (const float*)d_in[9];
    const float* fb1    = (const float*)d_in[10];
    const float* fW2    = (const float*)d_in[11];
    const float* fb2    = (const float*)d_in[12];

    float* out1 = (float*)d_out;                               // [B,T,D]
    float* attn = (float*)d_out + (size_t)BB * TT * DD;        // [B,H,T,T]

    float *nX, *QKV, *NV, *SS, *PRE, *PREr, *HID, *WTS;
    cudaGetSymbolAddress((void**)&nX,    g_nX);
    cudaGetSymbolAddress((void**)&QKV,   g_QKV);
    cudaGetSymbolAddress((void**)&NV,    g_NV);
    cudaGetSymbolAddress((void**)&SS,    g_SS);
    cudaGetSymbolAddress((void**)&PRE,   g_PRE);
    cudaGetSymbolAddress((void**)&PREr,  g_PREr);
    cudaGetSymbolAddress((void**)&HID,   g_HID);
    cudaGetSymbolAddress((void**)&WTS,   g_WTS);

    const size_t M1 = 1024*1024;
    const size_t RD = (size_t)ROWS * DD;
    // transposed [N][K] rounded weights
    float* WQKVt = WTS;              // 3 x [1024][1024]
    float* WOt   = WTS + 3*M1;       // [1024][1024]
    float* fW1t  = WTS + 4*M1;       // [4096][1024]
    float* fW2t  = WTS + 8*M1;       // [1024][4096]

    float* Q  = QKV;
    float* K_ = QKV + RD;
    float* V  = QKV + 2*RD;
    float* Vt = nX;                  // nX dead after QKV; exactly BB*HH*PP*TT floats

    static bool attrDone = false;
    if (!attrDone) {
        cudaFuncSetAttribute(mma_gemm<128,2,false,3>, cudaFuncAttributeMaxDynamicSharedMemorySize, (int)smemBytes(128,2,3));
        cudaFuncSetAttribute(mma_gemm<64,2,false,4>,  cudaFuncAttributeMaxDynamicSharedMemorySize, (int)smemBytes(64,2,4));
        attrDone = true;
    }

    const size_t TT2 = (size_t)TT * TT;
    const size_t TD  = (size_t)TT * DD;

    // 0. transpose + round weights -> [N][K]
    transpose_round<<<dim3(32, 32),  256>>>(WQ,  WQKVt,        DD, DD, 1);
    transpose_round<<<dim3(32, 32),  256>>>(WK,  WQKVt + 1*M1, DD, DD, 1);
    transpose_round<<<dim3(32, 32),  256>>>(WV,  WQKVt + 2*M1, DD, DD, 1);
    transpose_round<<<dim3(32, 32),  256>>>(WO,  WOt,  DD, DD, 0);
    transpose_round<<<dim3(32, 128), 256>>>(fW1, fW1t, DD, FFD, 0);
    transpose_round<<<dim3(128, 32), 256>>>(fW2, fW2t, FFD, DD, 0);

    // 1. nX = round(LN(X))
    ln_kernel<<<ROWS, 256>>>(X, attn_g, attn_b, nullptr, nullptr, nX);

    // 2. QKV in one launch: z selects weight block / output block
    mma_gemm<128,2,false,3><<<dim3(DD/128, ROWS/128, 3), 256, smemBytes(128,2,3)>>>(
        nX, DD, 0, 0,
        WQKVt, DD, 0, M1,
        QKV, DD, 0, RD,
        DD, nullptr, nullptr, 0, 1.0f, 1);

    // 2b. Vt[(b,h)][p][k] = V[b,k,h,p]   (overwrites nX — dead from here on)
    v_transpose<<<dim3(TT/32, PP/32, BB*HH), 256>>>(V, Vt);

    // 3. scores -> raw scaled S in attn region
    mma_gemm<128,2,false,3><<<dim3(TT/128, TT/128, BB*HH), 256, smemBytes(128,2,3)>>>(
        K_, DD, TD, 64,
        Q,  DD, TD, 64,
        attn, TT, 16*TT2, TT2,
        PP, nullptr, nullptr, 0, 0.125f, 0);

    // 4. softmax in place
    softmax_kernel<<<BB*HH*TT, 256>>>(attn);

    // 5. NV = attn @ V  (A raw -> HW tf32 truncation; B = Vt via ldmatrix)
    mma_gemm<64,2,false,4><<<dim3(1, TT/128, BB*HH), 256, smemBytes(64,2,4)>>>(
        attn, TT, 16*TT2, TT2,
        Vt,   TT, TD, (size_t)PP*TT,
        NV,   DD, TD, 64,
        TT, nullptr, nullptr, 0, 1.0f, 1);

    // 6. SS = NV @ WO
    mma_gemm<128,2,false,3><<<dim3(DD/128, ROWS/128, 1), 256, smemBytes(128,2,3)>>>(
        NV, DD, 0,0, WOt, DD, 0,0, SS, DD, 0,0, DD, nullptr, nullptr, 0, 1.0f, 0);

    // 7. PRE = X + LN(SS)  (full + rounded copy)
    ln_kernel<<<ROWS, 256>>>(SS, ff_g, ff_b, X, PRE, PREr);

    // 8. HID = round(gelu(PREr @ fW1 + fb1))
    mma_gemm<128,2,false,3><<<dim3(FFD/128, ROWS/128, 1), 256, smemBytes(128,2,3)>>>(
        PREr, DD, 0,0, fW1t, DD, 0,0, HID, FFD, 0,0, DD, fb1, nullptr, 1, 1.0f, 1);

    // 9. out1 = HID @ fW2 + fb2 + PRE
    mma_gemm<128,2,false,3><<<dim3(DD/128, ROWS/128, 1), 256, smemBytes(128,2,3)>>>(
        HID, FFD, 0,0, fW2t, FFD, 0,0, out1, DD, 0,0, FFD, fb2, PRE, 0, 1.0f, 0);
}

// round 15
// speedup vs baseline: 1.0087x; 1.0087x over previous
#include <cuda_runtime.h>
#include <cuda_bf16.h>
#include <math.h>
#include <stdint.h>
#include <cstdint>

// Problem shape
#define BB 4
#define TT 2048
#define DD 1024
#define HH 16
#define PP 64
#define FFD 4096
#define ROWS (BB*TT)          // 8192

// ---------------- scratch (device globals; no allocation allowed) -------------
__device__ float g_nX  [ROWS*DD];
__device__ float g_QKV [3*ROWS*DD];
__device__ float g_NV  [ROWS*DD];
__device__ float g_SS  [ROWS*DD];
__device__ float g_PRE [ROWS*DD];
__device__ float g_PREr[ROWS*DD];
__device__ float g_HID [ROWS*FFD];
__device__ float g_WTS [12*1024*1024];   // transposed+rounded weights: WQ|WK|WV|WO|fW1|fW2

__device__ __forceinline__ float gelu_f(float x) {
    return 0.5f * x * (1.0f + erff(x * 0.70710678118654752440f));
}

__device__ __forceinline__ uint32_t f2tf32(float x) {
    uint32_t u;
    asm("cvt.rna.tf32.f32 %0, %1;" : "=r"(u) : "f"(x));
    return u;
}
__device__ __forceinline__ float roundtf(float x) { return __uint_as_float(f2tf32(x)); }

__device__ __forceinline__ void mma8(float* c, const uint32_t* a, uint32_t b0, uint32_t b1) {
    asm volatile(
        "mma.sync.aligned.m16n8k8.row.col.f32.tf32.tf32.f32 "
        "{%0,%1,%2,%3}, {%4,%5,%6,%7}, {%8,%9}, {%0,%1,%2,%3};\n"
        : "+f"(c[0]), "+f"(c[1]), "+f"(c[2]), "+f"(c[3])
        : "r"(a[0]), "r"(a[1]), "r"(a[2]), "r"(a[3]), "r"(b0), "r"(b1));
}

__device__ __forceinline__ void ldsm4(uint32_t& r0, uint32_t& r1, uint32_t& r2, uint32_t& r3,
                                      uint32_t addr) {
    asm volatile("ldmatrix.sync.aligned.m8n8.x4.shared.b16 {%0,%1,%2,%3}, [%4];"
                 : "=r"(r0), "=r"(r1), "=r"(r2), "=r"(r3) : "r"(addr));
}

__device__ __forceinline__ void cp16(float* dst, const float* src) {
    uint32_t d = (uint32_t)__cvta_generic_to_shared(dst);
    asm volatile("cp.async.cg.shared.global [%0], [%1], 16;\n" :: "r"(d), "l"(src));
}
__device__ __forceinline__ void cp_commit() { asm volatile("cp.async.commit_group;\n"); }
template<int N>
__device__ __forceinline__ void cp_waitN() { asm volatile("cp.async.wait_group %0;\n" :: "n"(N)); }

// ---------------- weight transpose + tf32 round -------------------------------
// mode 0: in is [K][N] row-major.  mode 1: in is [H][K][64], logical col n=h*64+p.
// out: [N][K] row-major, tf32-rounded. grid (K/32, N/32, nz), 256 threads.
// grid.z selects input in0/in1/in2 and output offset z*K*N (QKV merge).
__global__ void transpose_round(const float* __restrict__ in0, const float* __restrict__ in1,
                                const float* __restrict__ in2, float* __restrict__ out,
                                int K, int N, int mode)
{
    __shared__ float tile[32][33];
    const float* in = (blockIdx.z == 0) ? in0 : (blockIdx.z == 1) ? in1 : in2;
    out += (size_t)blockIdx.z * K * N;
    const int k0 = blockIdx.x * 32;
    const int n0 = blockIdx.y * 32;
    const int tx = threadIdx.x & 31;
    const int ty = threadIdx.x >> 5;     // 0..7
    #pragma unroll
    for (int i = 0; i < 4; i++) {
        int k = k0 + ty + i * 8;
        int n = n0 + tx;
        float v;
        if (mode == 0) v = in[(size_t)k * N + n];
        else           v = in[(size_t)(n >> 6) * ((size_t)K * 64) + (size_t)k * 64 + (n & 63)];
        tile[ty + i * 8][tx] = roundtf(v);
    }
    __syncthreads();
    #pragma unroll
    for (int i = 0; i < 4; i++) {
        int n = n0 + ty + i * 8;
        int k = k0 + tx;
        out[(size_t)n * K + k] = tile[tx][ty + i * 8];
    }
}

// ---------------- LayerNorm (warp-shuffle reduction) ---------------------------
__global__ void ln_kernel(const float* __restrict__ X, const float* __restrict__ gg,
                          const float* __restrict__ bb, const float* __restrict__ res,
                          float* __restrict__ Yfull, float* __restrict__ Yr)
{
    __shared__ float rs[8], rq[8];
    const int row = blockIdx.x;
    const int t = threadIdx.x;
    const int lane = t & 31, w = t >> 5;
    float4 v = ((const float4*)(X + (size_t)row * DD))[t];
    float s = v.x + v.y + v.z + v.w;
    float q = v.x*v.x + v.y*v.y + v.z*v.z + v.w*v.w;
    #pragma unroll
    for (int o = 16; o > 0; o >>= 1) {
        s += __shfl_xor_sync(0xffffffffu, s, o);
        q += __shfl_xor_sync(0xffffffffu, q, o);
    }
    if (lane == 0) { rs[w] = s; rq[w] = q; }
    __syncthreads();
    s = rs[0]+rs[1]+rs[2]+rs[3]+rs[4]+rs[5]+rs[6]+rs[7];
    q = rq[0]+rq[1]+rq[2]+rq[3]+rq[4]+rq[5]+rq[6]+rq[7];
    const float mu  = s * (1.0f/1024.0f);
    const float var = q * (1.0f/1024.0f) - mu*mu;
    const float inv = rsqrtf(var + 1e-5f);
    float4 g4 = ((const float4*)gg)[t];
    float4 b4 = ((const float4*)bb)[t];
    float4 o;
    o.x = (v.x-mu)*inv*g4.x + b4.x;
    o.y = (v.y-mu)*inv*g4.y + b4.y;
    o.z = (v.z-mu)*inv*g4.z + b4.z;
    o.w = (v.w-mu)*inv*g4.w + b4.w;
    if (res) {
        float4 r = ((const float4*)(res + (size_t)row * DD))[t];
        o.x += r.x; o.y += r.y; o.z += r.z; o.w += r.w;
    }
    if (Yfull) ((float4*)(Yfull + (size_t)row * DD))[t] = o;
    if (Yr) {
        float4 rr = make_float4(roundtf(o.x), roundtf(o.y), roundtf(o.z), roundtf(o.w));
        ((float4*)(Yr + (size_t)row * DD))[t] = rr;
    }
}

// ---------------- in-place row softmax (row length 2048, vectorized) ----------
__global__ void softmax_kernel(float* __restrict__ S)
{
    __shared__ float red[8];
    const size_t row = blockIdx.x;
    float4* p = (float4*)(S + row * (size_t)TT);
    const int t = threadIdx.x;            // 256 threads, 2 float4 each
    const int lane = t & 31, w = t >> 5;

    float4 v0 = p[t];
    float4 v1 = p[t + 256];
    float mx = fmaxf(fmaxf(fmaxf(v0.x, v0.y), fmaxf(v0.z, v0.w)),
                     fmaxf(fmaxf(v1.x, v1.y), fmaxf(v1.z, v1.w)));
    #pragma unroll
    for (int o = 16; o > 0; o >>= 1)
        mx = fmaxf(mx, __shfl_xor_sync(0xffffffffu, mx, o));
    if (lane == 0) red[w] = mx;
    __syncthreads();
    mx = fmaxf(fmaxf(fmaxf(red[0], red[1]), fmaxf(red[2], red[3])),
               fmaxf(fmaxf(red[4], red[5]), fmaxf(red[6], red[7])));
    __syncthreads();

    float4 e0, e1;
    e0.x = __expf(v0.x - mx); e0.y = __expf(v0.y - mx);
    e0.z = __expf(v0.z - mx); e0.w = __expf(v0.w - mx);
    e1.x = __expf(v1.x - mx); e1.y = __expf(v1.y - mx);
    e1.z = __expf(v1.z - mx); e1.w = __expf(v1.w - mx);
    float sum = (e0.x + e0.y) + (e0.z + e0.w) + (e1.x + e1.y) + (e1.z + e1.w);
    #pragma unroll
    for (int o = 16; o > 0; o >>= 1)
        sum += __shfl_xor_sync(0xffffffffu, sum, o);
    if (lane == 0) red[w] = sum;
    __syncthreads();
    sum = (red[0]+red[1]) + (red[2]+red[3]) + (red[4]+red[5]) + (red[6]+red[7]);
    const float inv = 1.0f / sum;

    e0.x *= inv; e0.y *= inv; e0.z *= inv; e0.w *= inv;
    e1.x *= inv; e1.y *= inv; e1.z *= inv; e1.w *= inv;
    p[t]       = e0;
    p[t + 256] = e1;
}

// =====================================================================
// Unified tf32 tensor-core GEMM, STAGES-deep cp.async pipeline, ldmatrix frags.
//   C[r][c] = act( scale * sum_k A[r][k]*B(k,c) + bias[c] ) + residual[r][c]
// BMODE: 0 -> B row-major [K,N]
//        2 -> B given as [N, K] row-major (smem tile n-major; B via ldmatrix)
// CVTA: cvt A fragments to tf32 after load (false -> HW RZ truncation or
//       A already rounded).
// =====================================================================
template<int BN, int BMODE, bool CVTA, int STAGES>
__global__ void __launch_bounds__(256, 2) mma_gemm(
    const float* __restrict__ A, int lda, size_t aOffB, size_t aOffH,
    const float* __restrict__ B, int ldb, size_t bOffB, size_t bOffH,
    float*       __restrict__ C, int ldc, size_t cOffB, size_t cOffH,
    int K, const float* __restrict__ bias, const float* __restrict__ residual,
    int act, float scale, int outRound)
{
    constexpr int BM = 128, BK = 32;
    constexpr int NT = BN / 32;
    constexpr int WN = BN / 4;
    constexpr int AROW = BK + 4;                    // 36
    constexpr int A_STAGE = BM * AROW;
    constexpr int BROW = (BMODE == 2) ? (BK + 4) : (BN + 8);
    constexpr int B_STAGE = (BMODE == 2) ? (BN * BROW) : (BK * BROW);

    extern __shared__ float sm[];
    float* AsBase = sm;
    float* BsBase = sm + STAGES * A_STAGE;
    const uint32_t smU = (uint32_t)__cvta_generic_to_shared(sm);
    const uint32_t bsU = smU + STAGES * A_STAGE * 4;

    const int tid  = threadIdx.x;
    const int lane = tid & 31;
    const int warp = tid >> 5;
    const int g  = lane >> 2;
    const int tq = lane & 3;
    const int wmBase = (warp & 1) * 64;
    const int wnBase = (warp >> 1) * WN;

    const int row0 = blockIdx.y * BM;
    const int col0 = blockIdx.x * BN;

    const int zb = blockIdx.z >> 4, zh = blockIdx.z & 15;
    A += (size_t)zb * aOffB + (size_t)zh * aOffH;
    B += (size_t)zb * bOffB + (size_t)zh * bOffH;
    C += (size_t)zb * cOffB + (size_t)zh * cOffH;

    const int nT = K >> 5;

    uint32_t aLane[4];
    #pragma unroll
    for (int mi = 0; mi < 4; mi++) {
        int r = wmBase + mi * 16 + (lane & 15);
        int c = (lane >> 4) << 2;
        aLane[mi] = (uint32_t)((r * AROW + c) * 4);
    }
    uint32_t bLane[NT > 1 ? NT / 2 : 1];
    if (BMODE == 2) {
        #pragma unroll
        for (int np = 0; np < NT / 2; np++) {
            int sel = lane >> 3;
            int nrow = wnBase + np * 16 + ((sel >> 1) << 3) + (lane & 7);
            int c = (sel & 1) << 2;
            bLane[np] = (uint32_t)((nrow * BROW + c) * 4);
        }
    }

    auto issueA = [&](int t, float* dst) {
        const float* Ak = A + (size_t)row0 * lda + t * BK;
        #pragma unroll
        for (int p = 0; p < 4; p++) {
            int chunk = tid + 256 * p;
            int r = chunk >> 3, c = (chunk & 7) * 4;
            cp16(dst + r * AROW + c, Ak + (size_t)r * lda + c);
        }
    };
    auto issueB = [&](int t, float* dst) {
        if (BMODE == 2) {
            constexpr int PB = (BN * 8) / 256;       // 4 for BN=128, 2 for BN=64
            const float* Bk = B + (size_t)col0 * ldb + t * BK;
            #pragma unroll
            for (int p = 0; p < PB; p++) {
                int chunk = tid + 256 * p;
                int r = chunk >> 3, c = (chunk & 7) * 4;
                cp16(dst + r * BROW + c, Bk + (size_t)r * ldb + c);
            }
        } else {
            constexpr int P   = (BN == 128) ? 4 : 2;
            constexpr int CSH = (BN == 128) ? 5 : 4;
            constexpr int CMK = (BN == 128) ? 31 : 15;
            const float* Bk = B + (size_t)(t * BK) * ldb + col0;
            #pragma unroll
            for (int p = 0; p < P; p++) {
                int chunk = tid + 256 * p;
                int k = chunk >> CSH, c = (chunk & CMK) * 4;
                cp16(dst + k * BROW + c, Bk + (size_t)k * ldb + c);
            }
        }
    };

    float acc[4][NT][4];
    #pragma unroll
    for (int i = 0; i < 4; i++)
        #pragma unroll
        for (int j = 0; j < NT; j++)
            #pragma unroll
            for (int l = 0; l < 4; l++) acc[i][j][l] = 0.0f;

    #pragma unroll
    for (int t = 0; t < STAGES - 1; t++) {
        if (t < nT) {
            issueA(t, AsBase + t * A_STAGE);
            issueB(t, BsBase + t * B_STAGE);
            cp_commit();
        }
    }

    int s = 0;
    for (int t = 0; t < nT; t++) {
        int rem = nT - 1 - t;
        if (rem >= STAGES - 2)      cp_waitN<STAGES - 2>();
        else if (STAGES >= 4 && rem == 2) cp_waitN<2>();
        else if (rem == 1)          cp_waitN<1>();
        else                        cp_waitN<0>();
        __syncthreads();

        const uint32_t aBaseS = smU + (uint32_t)(s * A_STAGE * 4);
        const uint32_t bBaseS = bsU + (uint32_t)(s * B_STAGE * 4);
        const float* Bsm = BsBase + s * B_STAGE;

        #pragma unroll
        for (int ks = 0; ks < 4; ks++) {
            const int kb = ks * 8;
            uint32_t bf[NT][2];
            if (BMODE == 2) {
                #pragma unroll
                for (int np = 0; np < NT / 2; np++)
                    ldsm4(bf[2*np][0], bf[2*np][1], bf[2*np+1][0], bf[2*np+1][1],
                          bBaseS + bLane[np] + kb * 4);
            } else {
                #pragma unroll
                for (int ni = 0; ni < NT; ni++) {
                    int n = wnBase + ni * 8 + g;
                    bf[ni][0] = __float_as_uint(Bsm[(size_t)(kb + tq)     * BROW + n]);
                    bf[ni][1] = __float_as_uint(Bsm[(size_t)(kb + tq + 4) * BROW + n]);
                }
            }
            #pragma unroll
            for (int mi = 0; mi < 4; mi++) {
                uint32_t af[4];
                ldsm4(af[0], af[1], af[2], af[3], aBaseS + aLane[mi] + kb * 4);
                if (CVTA) {
                    af[0] = f2tf32(__uint_as_float(af[0]));
                    af[1] = f2tf32(__uint_as_float(af[1]));
                    af[2] = f2tf32(__uint_as_float(af[2]));
                    af[3] = f2tf32(__uint_as_float(af[3]));
                }
                #pragma unroll
                for (int ni = 0; ni < NT; ni++)
                    mma8(acc[mi][ni], af, bf[ni][0], bf[ni][1]);
            }
        }

        int tn = t + STAGES - 1;
        if (tn < nT) {
            int sn = tn - (tn / STAGES) * STAGES;
            issueA(tn, AsBase + sn * A_STAGE);
            issueB(tn, BsBase + sn * B_STAGE);
            cp_commit();
        }
        s++; if (s == STAGES) s = 0;
    }

    #pragma unroll
    for (int mi = 0; mi < 4; mi++) {
        int r0 = row0 + wmBase + mi * 16 + g;
        #pragma unroll
        for (int ni = 0; ni < NT; ni++) {
            int col = col0 + wnBase + ni * 8 + 2 * tq;
            float b0 = 0.0f, b1 = 0.0f;
            if (bias) { b0 = bias[col]; b1 = bias[col + 1]; }
            #pragma unroll
            for (int half = 0; half < 2; half++) {
                int r = r0 + half * 8;
                float x0 = acc[mi][ni][half*2 + 0] * scale + b0;
                float x1 = acc[mi][ni][half*2 + 1] * scale + b1;
                if (act) { x0 = gelu_f(x0); x1 = gelu_f(x1); }
                if (residual) {
                    float2 rr = *(const float2*)(residual + (size_t)r * ldc + col);
                    x0 += rr.x; x1 += rr.y;
                }
                if (outRound) { x0 = roundtf(x0); x1 = roundtf(x1); }
                *(float2*)(C + (size_t)r * ldc + col) = make_float2(x0, x1);
            }
        }
    }
}

// smem sizes (bytes)
static constexpr size_t smemBytes(int BN, int BMODE, int stages) {
    size_t aStage = 128 * 36;
    size_t bStage = (BMODE == 2) ? (size_t)BN * 36 : (size_t)32 * (BN + 8);
    return (size_t)stages * (aStage + bStage) * 4;
}

// -----------------------------------------------------------------------------
extern "C" void kernel_launch(void* const* d_in, const int* in_sizes, int n_in,
                              void* d_out, int out_size)
{
    const float* X      = (const float*)d_in[0];
    const float* WQ     = (const float*)d_in[1];
    const float* WK     = (const float*)d_in[2];
    const float* WV     = (const float*)d_in[3];
    const float* WO     = (const float*)d_in[4];
    const float* attn_g = (const float*)d_in[5];
    const float* attn_b = (const float*)d_in[6];
    const float* ff_g   = (const float*)d_in[7];
    const float* ff_b   = (const float*)d_in[8];
    const float* fW1    = (const float*)d_in[9];
    const float* fb1    = (const float*)d_in[10];
    const float* fW2    = (const float*)d_in[11];
    const float* fb2    = (const float*)d_in[12];

    float* out1 = (float*)d_out;                               // [B,T,D]
    float* attn = (float*)d_out + (size_t)BB * TT * DD;        // [B,H,T,T]

    float *nX, *QKV, *NV, *SS, *PRE, *PREr, *HID, *WTS;
    cudaGetSymbolAddress((void**)&nX,    g_nX);
    cudaGetSymbolAddress((void**)&QKV,   g_QKV);
    cudaGetSymbolAddress((void**)&NV,    g_NV);
    cudaGetSymbolAddress((void**)&SS,    g_SS);
    cudaGetSymbolAddress((void**)&PRE,   g_PRE);
    cudaGetSymbolAddress((void**)&PREr,  g_PREr);
    cudaGetSymbolAddress((void**)&HID,   g_HID);
    cudaGetSymbolAddress((void**)&WTS,   g_WTS);

    const size_t M1 = 1024*1024;
    const size_t RD = (size_t)ROWS * DD;
    // transposed [N][K] rounded weights
    float* WQKVt = WTS;              // 3 x [1024][1024]
    float* WOt   = WTS + 3*M1;       // [1024][1024]
    float* fW1t  = WTS + 4*M1;       // [4096][1024]
    float* fW2t  = WTS + 8*M1;       // [1024][4096]

    float* Q  = QKV;
    float* K_ = QKV + RD;
    float* V  = QKV + 2*RD;

    static bool attrDone = false;
    if (!attrDone) {
        cudaFuncSetAttribute(mma_gemm<128,2,false,3>, cudaFuncAttributeMaxDynamicSharedMemorySize, (int)smemBytes(128,2,3));
        cudaFuncSetAttribute(mma_gemm<64,0,false,4>,  cudaFuncAttributeMaxDynamicSharedMemorySize, (int)smemBytes(64,0,4));
        attrDone = true;
    }

    const size_t TT2 = (size_t)TT * TT;
    const size_t TD  = (size_t)TT * DD;

    // 0. transpose + round weights -> [N][K]  (QKV merged into one launch)
    transpose_round<<<dim3(32, 32, 3), 256>>>(WQ, WK, WV, WQKVt, DD, DD, 1);
    transpose_round<<<dim3(32, 32),    256>>>(WO,  WO,  WO,  WOt,  DD, DD, 0);
    transpose_round<<<dim3(32, 128),   256>>>(fW1, fW1, fW1, fW1t, DD, FFD, 0);
    transpose_round<<<dim3(128, 32),   256>>>(fW2, fW2, fW2, fW2t, FFD, DD, 0);

    // 1. nX = round(LN(X))
    ln_kernel<<<ROWS, 256>>>(X, attn_g, attn_b, nullptr, nullptr, nX);

    // 2. QKV in one launch: z selects weight block / output block
    mma_gemm<128,2,false,3><<<dim3(DD/128, ROWS/128, 3), 256, smemBytes(128,2,3)>>>(
        nX, DD, 0, 0,
        WQKVt, DD, 0, M1,
        QKV, DD, 0, RD,
        DD, nullptr, nullptr, 0, 1.0f, 1);

    // 3. scores -> raw scaled S in attn region
    mma_gemm<128,2,false,3><<<dim3(TT/128, TT/128, BB*HH), 256, smemBytes(128,2,3)>>>(
        K_, DD, TD, 64,
        Q,  DD, TD, 64,
        attn, TT, 16*TT2, TT2,
        PP, nullptr, nullptr, 0, 0.125f, 0);

    // 4. softmax in place
    softmax_kernel<<<BB*HH*TT, 256>>>(attn);

    // 5. NV = attn @ V  (A fed raw: HW tf32 truncation; 4-stage pipeline)
    mma_gemm<64,0,false,4><<<dim3(1, TT/128, BB*HH), 256, smemBytes(64,0,4)>>>(
        attn, TT, 16*TT2, TT2,
        V,    DD, TD, 64,
        NV,   DD, TD, 64,
        TT, nullptr, nullptr, 0, 1.0f, 1);

    // 6. SS = NV @ WO
    mma_gemm<128,2,false,3><<<dim3(DD/128, ROWS/128, 1), 256, smemBytes(128,2,3)>>>(
        NV, DD, 0,0, WOt, DD, 0,0, SS, DD, 0,0, DD, nullptr, nullptr, 0, 1.0f, 0);

    // 7. PRE = X + LN(SS)  (full + rounded copy)
    ln_kernel<<<ROWS, 256>>>(SS, ff_g, ff_b, X, PRE, PREr);

    // 8. HID = round(gelu(PREr @ fW1 + fb1))
    mma_gemm<128,2,false,3><<<dim3(FFD/128, ROWS/128, 1), 256, smemBytes(128,2,3)>>>(
        PREr, DD, 0,0, fW1t, DD, 0,0, HID, FFD, 0,0, DD, fb1, nullptr, 1, 1.0f, 1);

    // 9. out1 = HID @ fW2 + fb2 + PRE
    mma_gemm<128,2,false,3><<<dim3(DD/128, ROWS/128, 1), 256, smemBytes(128,2,3)>>>(
        HID, FFD, 0,0, fW2t, FFD, 0,0, out1, DD, 0,0, FFD, fb2, PRE, 0, 1.0f, 0);
}